// round 1
// baseline (speedup 1.0000x reference)
#include <cuda_runtime.h>

// Problem constants (fixed shapes for this problem)
#define HDIM   1024
#define NHEAD  16
#define HEADD  64
#define BATCH  4
#define SEQ    2048
#define BSROWS (BATCH * SEQ)   // 8192

// Scratch (allocation-free rule: __device__ globals)
__device__ float g_q[(size_t)BSROWS * HDIM];
__device__ float g_k[(size_t)BSROWS * HDIM];
__device__ float g_v[(size_t)BSROWS * HDIM];
__device__ float g_ctx[(size_t)BSROWS * HDIM];

// ---------------------------------------------------------------------------
// Helpers
// ---------------------------------------------------------------------------
__device__ __forceinline__ float tf32r(float x) {
    unsigned u;
    asm("cvt.rna.tf32.f32 %0, %1;" : "=r"(u) : "f"(x));
    return __uint_as_float(u);
}

__device__ __forceinline__ void mma8(float* c,
                                     unsigned a0, unsigned a1, unsigned a2, unsigned a3,
                                     unsigned b0, unsigned b1) {
    asm volatile(
        "mma.sync.aligned.m16n8k8.row.col.f32.tf32.tf32.f32 "
        "{%0,%1,%2,%3}, {%4,%5,%6,%7}, {%8,%9}, {%0,%1,%2,%3};"
        : "+f"(c[0]), "+f"(c[1]), "+f"(c[2]), "+f"(c[3])
        : "r"(a0), "r"(a1), "r"(a2), "r"(a3), "r"(b0), "r"(b1));
}

// ---------------------------------------------------------------------------
// Generic GEMM: C[m,n] = sum_k A[m,k] * W[n,k] + bias[n]
// A: [M,1024] row-major, W: [1024,1024] row-major (both K-contiguous)
// Tile: 128x128x32, 256 threads (8 warps: 4 in M x 2 in N, warp tile 32x64)
// TF32 mma m16n8k8, fp32 accumulate. Register-prefetch double buffering.
// grid = (N/128, M/128)
// ---------------------------------------------------------------------------
__global__ __launch_bounds__(256, 1)
void gemm128(const float* __restrict__ A, const float* __restrict__ W,
             const float* __restrict__ bias, float* __restrict__ C) {
    const int tid  = threadIdx.x;
    const int lane = tid & 31, wid = tid >> 5;
    const int g = lane >> 2, tg = lane & 3;
    const int wm = wid & 3, wn = wid >> 2;
    const int bm = blockIdx.y * 128, bn = blockIdx.x * 128;
    const int lrow = tid >> 3;            // 0..31
    const int lcol = (tid & 7) * 4;       // 0..28

    // stride 36 (== 4 mod 32) -> conflict-free fragment loads
    __shared__ float As[128][36];
    __shared__ float Bs[128][36];

    float acc[2][8][4];
#pragma unroll
    for (int mt = 0; mt < 2; mt++)
#pragma unroll
        for (int nt = 0; nt < 8; nt++)
#pragma unroll
            for (int i = 0; i < 4; i++) acc[mt][nt][i] = 0.f;

    const float* Ag = A + (size_t)(bm + lrow) * HDIM + lcol;
    const float* Wg = W + (size_t)(bn + lrow) * HDIM + lcol;

    float4 pa[4], pb[4];
#pragma unroll
    for (int i = 0; i < 4; i++) {
        pa[i] = *(const float4*)(Ag + (size_t)i * 32 * HDIM);
        pb[i] = *(const float4*)(Wg + (size_t)i * 32 * HDIM);
    }

    for (int kt = 0; kt < 32; kt++) {
        // commit current prefetch to smem (pre-rounded to tf32)
#pragma unroll
        for (int i = 0; i < 4; i++) {
            float4 a = pa[i];
            a.x = tf32r(a.x); a.y = tf32r(a.y); a.z = tf32r(a.z); a.w = tf32r(a.w);
            *(float4*)&As[lrow + 32 * i][lcol] = a;
            float4 b = pb[i];
            b.x = tf32r(b.x); b.y = tf32r(b.y); b.z = tf32r(b.z); b.w = tf32r(b.w);
            *(float4*)&Bs[lrow + 32 * i][lcol] = b;
        }
        __syncthreads();

        // issue next tile's global loads (overlap with compute)
        if (kt < 31) {
#pragma unroll
            for (int i = 0; i < 4; i++) {
                pa[i] = *(const float4*)(Ag + (kt + 1) * 32 + (size_t)i * 32 * HDIM);
                pb[i] = *(const float4*)(Wg + (kt + 1) * 32 + (size_t)i * 32 * HDIM);
            }
        }

#pragma unroll
        for (int ks = 0; ks < 4; ks++) {
            unsigned af[2][4];
#pragma unroll
            for (int mt = 0; mt < 2; mt++) {
                int r = wm * 32 + mt * 16 + g;
                af[mt][0] = __float_as_uint(As[r][ks * 8 + tg]);
                af[mt][1] = __float_as_uint(As[r + 8][ks * 8 + tg]);
                af[mt][2] = __float_as_uint(As[r][ks * 8 + tg + 4]);
                af[mt][3] = __float_as_uint(As[r + 8][ks * 8 + tg + 4]);
            }
#pragma unroll
            for (int nt = 0; nt < 8; nt++) {
                int n = wn * 64 + nt * 8 + g;
                unsigned b0 = __float_as_uint(Bs[n][ks * 8 + tg]);
                unsigned b1 = __float_as_uint(Bs[n][ks * 8 + tg + 4]);
#pragma unroll
                for (int mt = 0; mt < 2; mt++)
                    mma8(acc[mt][nt], af[mt][0], af[mt][1], af[mt][2], af[mt][3], b0, b1);
            }
        }
        __syncthreads();
    }

    // epilogue: bias + store
#pragma unroll
    for (int mt = 0; mt < 2; mt++) {
        int r0 = bm + wm * 32 + mt * 16 + g;
#pragma unroll
        for (int nt = 0; nt < 8; nt++) {
            int n = bn + wn * 64 + nt * 8 + 2 * tg;
            float b0 = bias[n], b1 = bias[n + 1];
            float2 v0 = make_float2(acc[mt][nt][0] + b0, acc[mt][nt][1] + b1);
            float2 v1 = make_float2(acc[mt][nt][2] + b0, acc[mt][nt][3] + b1);
            *(float2*)&C[(size_t)r0 * HDIM + n]       = v0;
            *(float2*)&C[(size_t)(r0 + 8) * HDIM + n] = v1;
        }
    }
}

// ---------------------------------------------------------------------------
// Flash attention: one CTA per (b, h, 64-row q tile). 128 threads (4 warps),
// warp w owns rows 16w..16w+15. Q fragments live in registers for all KV
// tiles. K tile smem is reused as the P (probs) buffer. Online softmax in
// exp2 domain (1/sqrt(HD) * log2(e) folded into Q). TF32 mma throughout.
// grid = (SEQ/64, NHEAD, BATCH)
// ---------------------------------------------------------------------------
__global__ __launch_bounds__(128, 1)
void attn_kernel(const float* __restrict__ q, const float* __restrict__ k,
                 const float* __restrict__ v, const float* __restrict__ mask,
                 float* __restrict__ ctx) {
    const int b = blockIdx.z, h = blockIdx.y, qt = blockIdx.x;
    const int tid  = threadIdx.x;
    const int lane = tid & 31, wid = tid >> 5;
    const int g = lane >> 2, tg = lane & 3;

    // KP: K tile (stride 68 == 4 mod 32), reused for Q staging and P buffer.
    // Vs: V tile (stride 72 == 8 mod 32) -> conflict-free PV B-fragment loads.
    __shared__ float KP[64][68];
    __shared__ float Vs[64][72];
    __shared__ float Msm[64];

    const float LOG2E  = 1.4426950408889634f;
    const float QSCALE = 0.125f * LOG2E;   // 1/sqrt(64) * log2(e)

    const float* qbase = q + (size_t)(b * SEQ + qt * 64) * HDIM + h * HEADD;
    const float* kbase = k + (size_t)(b * SEQ) * HDIM + h * HEADD;
    const float* vbase = v + (size_t)(b * SEQ) * HDIM + h * HEADD;
    const float* mbase = mask + (size_t)b * SEQ;

    // ---- stage Q tile through KP, pull fragments into registers ----
#pragma unroll
    for (int i = 0; i < 8; i++) {
        int idx = tid + i * 128;
        int r = idx >> 4, c4 = (idx & 15) * 4;
        *(float4*)&KP[r][c4] = *(const float4*)&qbase[(size_t)r * HDIM + c4];
    }
    __syncthreads();

    unsigned qf[8][4];
    {
        int r = wid * 16 + g;
#pragma unroll
        for (int ks = 0; ks < 8; ks++) {
            qf[ks][0] = __float_as_uint(tf32r(KP[r][ks * 8 + tg] * QSCALE));
            qf[ks][1] = __float_as_uint(tf32r(KP[r + 8][ks * 8 + tg] * QSCALE));
            qf[ks][2] = __float_as_uint(tf32r(KP[r][ks * 8 + tg + 4] * QSCALE));
            qf[ks][3] = __float_as_uint(tf32r(KP[r + 8][ks * 8 + tg + 4] * QSCALE));
        }
    }

    float oacc[8][4];
#pragma unroll
    for (int nt = 0; nt < 8; nt++)
#pragma unroll
        for (int i = 0; i < 4; i++) oacc[nt][i] = 0.f;
    float m0 = -1e30f, m1 = -1e30f, l0 = 0.f, l1 = 0.f;

    const int r0 = wid * 16 + g, r1 = r0 + 8;

    for (int kt = 0; kt < SEQ / 64; kt++) {
        __syncthreads();   // previous iteration fully done with KP/Vs

        // load K tile (tf32-rounded) and V tile (tf32-rounded)
#pragma unroll
        for (int i = 0; i < 8; i++) {
            int idx = tid + i * 128;
            int r = idx >> 4, c4 = (idx & 15) * 4;
            float4 kv = *(const float4*)&kbase[(size_t)(kt * 64 + r) * HDIM + c4];
            kv.x = tf32r(kv.x); kv.y = tf32r(kv.y); kv.z = tf32r(kv.z); kv.w = tf32r(kv.w);
            *(float4*)&KP[r][c4] = kv;
            float4 vv = *(const float4*)&vbase[(size_t)(kt * 64 + r) * HDIM + c4];
            vv.x = tf32r(vv.x); vv.y = tf32r(vv.y); vv.z = tf32r(vv.z); vv.w = tf32r(vv.w);
            *(float4*)&Vs[r][c4] = vv;
        }
        if (tid < 64) Msm[tid] = mbase[kt * 64 + tid] * LOG2E;
        __syncthreads();

        // ---- S = (Q * scale) @ K^T  (already in log2 domain) ----
        float sacc[8][4];
#pragma unroll
        for (int nt = 0; nt < 8; nt++)
#pragma unroll
            for (int i = 0; i < 4; i++) sacc[nt][i] = 0.f;

#pragma unroll
        for (int ks = 0; ks < 8; ks++) {
#pragma unroll
            for (int nt = 0; nt < 8; nt++) {
                unsigned b0 = __float_as_uint(KP[nt * 8 + g][ks * 8 + tg]);
                unsigned b1 = __float_as_uint(KP[nt * 8 + g][ks * 8 + tg + 4]);
                mma8(sacc[nt], qf[ks][0], qf[ks][1], qf[ks][2], qf[ks][3], b0, b1);
            }
        }

        // ---- online softmax ----
        float rmax0 = -1e30f, rmax1 = -1e30f;
#pragma unroll
        for (int nt = 0; nt < 8; nt++) {
            float mk0 = Msm[nt * 8 + 2 * tg], mk1 = Msm[nt * 8 + 2 * tg + 1];
            sacc[nt][0] += mk0; sacc[nt][1] += mk1;
            sacc[nt][2] += mk0; sacc[nt][3] += mk1;
            rmax0 = fmaxf(rmax0, fmaxf(sacc[nt][0], sacc[nt][1]));
            rmax1 = fmaxf(rmax1, fmaxf(sacc[nt][2], sacc[nt][3]));
        }
        rmax0 = fmaxf(rmax0, __shfl_xor_sync(0xffffffffu, rmax0, 1));
        rmax0 = fmaxf(rmax0, __shfl_xor_sync(0xffffffffu, rmax0, 2));
        rmax1 = fmaxf(rmax1, __shfl_xor_sync(0xffffffffu, rmax1, 1));
        rmax1 = fmaxf(rmax1, __shfl_xor_sync(0xffffffffu, rmax1, 2));

        float mn0 = fmaxf(m0, rmax0), mn1 = fmaxf(m1, rmax1);
        float sc0 = exp2f(m0 - mn0), sc1 = exp2f(m1 - mn1);
        m0 = mn0; m1 = mn1;

        float pv[8][4];
        float rs0 = 0.f, rs1 = 0.f;
#pragma unroll
        for (int nt = 0; nt < 8; nt++) {
            pv[nt][0] = exp2f(sacc[nt][0] - m0);
            pv[nt][1] = exp2f(sacc[nt][1] - m0);
            pv[nt][2] = exp2f(sacc[nt][2] - m1);
            pv[nt][3] = exp2f(sacc[nt][3] - m1);
            rs0 += pv[nt][0] + pv[nt][1];
            rs1 += pv[nt][2] + pv[nt][3];
            oacc[nt][0] *= sc0; oacc[nt][1] *= sc0;
            oacc[nt][2] *= sc1; oacc[nt][3] *= sc1;
        }
        rs0 += __shfl_xor_sync(0xffffffffu, rs0, 1);
        rs0 += __shfl_xor_sync(0xffffffffu, rs0, 2);
        rs1 += __shfl_xor_sync(0xffffffffu, rs1, 1);
        rs1 += __shfl_xor_sync(0xffffffffu, rs1, 2);
        l0 = l0 * sc0 + rs0;
        l1 = l1 * sc1 + rs1;

        __syncthreads();   // everyone done reading K tile before P overwrites it

        // ---- write P (tf32-rounded) into KP; warp-private rows ----
#pragma unroll
        for (int nt = 0; nt < 8; nt++) {
            int c = nt * 8 + 2 * tg;
            KP[r0][c]     = tf32r(pv[nt][0]);
            KP[r0][c + 1] = tf32r(pv[nt][1]);
            KP[r1][c]     = tf32r(pv[nt][2]);
            KP[r1][c + 1] = tf32r(pv[nt][3]);
        }
        __syncwarp();

        // ---- O += P @ V ----
#pragma unroll
        for (int ks = 0; ks < 8; ks++) {
            unsigned a0 = __float_as_uint(KP[r0][ks * 8 + tg]);
            unsigned a1 = __float_as_uint(KP[r1][ks * 8 + tg]);
            unsigned a2 = __float_as_uint(KP[r0][ks * 8 + tg + 4]);
            unsigned a3 = __float_as_uint(KP[r1][ks * 8 + tg + 4]);
#pragma unroll
            for (int nt = 0; nt < 8; nt++) {
                unsigned b0 = __float_as_uint(Vs[ks * 8 + tg][nt * 8 + g]);
                unsigned b1 = __float_as_uint(Vs[ks * 8 + tg + 4][nt * 8 + g]);
                mma8(oacc[nt], a0, a1, a2, a3, b0, b1);
            }
        }
    }

    // ---- epilogue: O / l -> ctx (B,S,H) ----
    float inv0 = 1.f / l0, inv1 = 1.f / l1;
    float* obase = ctx + (size_t)(b * SEQ + qt * 64) * HDIM + h * HEADD;
#pragma unroll
    for (int nt = 0; nt < 8; nt++) {
        int c = nt * 8 + 2 * tg;
        float2 v0 = make_float2(oacc[nt][0] * inv0, oacc[nt][1] * inv0);
        float2 v1 = make_float2(oacc[nt][2] * inv1, oacc[nt][3] * inv1);
        *(float2*)&obase[(size_t)(wid * 16 + g) * HDIM + c]     = v0;
        *(float2*)&obase[(size_t)(wid * 16 + g + 8) * HDIM + c] = v1;
    }
}

// ---------------------------------------------------------------------------
// Launch
// ---------------------------------------------------------------------------
extern "C" void kernel_launch(void* const* d_in, const int* in_sizes, int n_in,
                              void* d_out, int out_size) {
    const float* hs   = (const float*)d_in[0];
    const float* mask = (const float*)d_in[1];
    const float* Wq   = (const float*)d_in[2];
    const float* bq   = (const float*)d_in[3];
    const float* Wk   = (const float*)d_in[4];
    const float* bk   = (const float*)d_in[5];
    const float* Wv   = (const float*)d_in[6];
    const float* bv   = (const float*)d_in[7];
    const float* Wo   = (const float*)d_in[8];
    const float* bo   = (const float*)d_in[9];
    float* out = (float*)d_out;

    float *q, *k, *v, *ctx;
    cudaGetSymbolAddress((void**)&q,   g_q);
    cudaGetSymbolAddress((void**)&k,   g_k);
    cudaGetSymbolAddress((void**)&v,   g_v);
    cudaGetSymbolAddress((void**)&ctx, g_ctx);

    dim3 ggrid(HDIM / 128, BSROWS / 128);      // (8, 64)
    gemm128<<<ggrid, 256>>>(hs, Wq, bq, q);
    gemm128<<<ggrid, 256>>>(hs, Wk, bk, k);
    gemm128<<<ggrid, 256>>>(hs, Wv, bv, v);

    dim3 agrid(SEQ / 64, NHEAD, BATCH);        // (32, 16, 4)
    attn_kernel<<<agrid, 128>>>(q, k, v, mask, ctx);

    gemm128<<<ggrid, 256>>>(ctx, Wo, bo, out);
}

// round 3
// speedup vs baseline: 2.6069x; 2.6069x over previous
#include <cuda_runtime.h>
#include <cuda_fp16.h>

#define HDIM   1024
#define NHEAD  16
#define HEADD  64
#define BATCH  4
#define SEQ    2048
#define BSROWS (BATCH * SEQ)   // 8192

// fp16 scratch (allocation-free rule: __device__ globals)
__device__ __half g_hs16[(size_t)BSROWS * HDIM];
__device__ __half g_wq16[(size_t)HDIM * HDIM];
__device__ __half g_wk16[(size_t)HDIM * HDIM];
__device__ __half g_wv16[(size_t)HDIM * HDIM];
__device__ __half g_wo16[(size_t)HDIM * HDIM];
__device__ __half g_q16[(size_t)BSROWS * HDIM];
__device__ __half g_k16[(size_t)BSROWS * HDIM];
__device__ __half g_vt16[(size_t)HDIM * BSROWS];   // [dim][b*S+s]
__device__ __half g_ctx16[(size_t)BSROWS * HDIM];

// ---------------------------------------------------------------------------
// helpers
// ---------------------------------------------------------------------------
__device__ __forceinline__ void mma16(float* c, const unsigned* a, unsigned b0, unsigned b1) {
    asm volatile(
        "mma.sync.aligned.m16n8k16.row.col.f32.f16.f16.f32 "
        "{%0,%1,%2,%3}, {%4,%5,%6,%7}, {%8,%9}, {%0,%1,%2,%3};"
        : "+f"(c[0]), "+f"(c[1]), "+f"(c[2]), "+f"(c[3])
        : "r"(a[0]), "r"(a[1]), "r"(a[2]), "r"(a[3]), "r"(b0), "r"(b1));
}

__device__ __forceinline__ float ex2(float x) {
    float r;
    asm("ex2.approx.ftz.f32 %0, %1;" : "=f"(r) : "f"(x));
    return r;
}

// XOR swizzle: 128B logical rows, 16B chunks, chunk ^= (row & 7). Conflict-free
// for both cp.async 16B stores and half2 fragment loads (bank = ((c>>4)^g)*4+tg).
__device__ __forceinline__ int swz(int r, int cbyte) {
    return r * 128 + ((((cbyte >> 4) ^ r) & 7) << 4) + (cbyte & 15);
}

#define CPA(dst, src) \
    asm volatile("cp.async.cg.shared.global [%0], [%1], 16;" :: "r"(dst), "l"(src))
#define CPA_COMMIT() asm volatile("cp.async.commit_group;" ::)
#define CPA_WAIT1()  asm volatile("cp.async.wait_group 1;" ::)
#define CPA_WAIT0()  asm volatile("cp.async.wait_group 0;" ::)

__device__ __forceinline__ unsigned h2pack(float lo, float hi) {
    __half2 h = __floats2half2_rn(lo, hi);
    return *(unsigned*)&h;
}

// ---------------------------------------------------------------------------
// fp32 -> fp16 convert
// ---------------------------------------------------------------------------
__global__ void cvt_kernel(const float* __restrict__ s, __half* __restrict__ d, int n4) {
    int stride = gridDim.x * blockDim.x;
    for (int i = blockIdx.x * blockDim.x + threadIdx.x; i < n4; i += stride) {
        float4 v = ((const float4*)s)[i];
        __half2 h0 = __floats2half2_rn(v.x, v.y);
        __half2 h1 = __floats2half2_rn(v.z, v.w);
        ((uint2*)d)[i] = make_uint2(*(unsigned*)&h0, *(unsigned*)&h1);
    }
}

// ---------------------------------------------------------------------------
// fp16 GEMM: C[m,n] = sum_k A[m,k]*B[n,k] + bias, K=1024, lda=ldb=1024.
// Tile 128x128xk64, 256 threads (8 warps: 4M x 2N, warp tile 32x64, mt=2).
// cp.async double buffer, swizzled smem, m16n8k16, fp32 accum.
// BIAS_ROW: bias indexed by m (for the V^T gemm). OUT_HALF: fp16 output.
// grid = (N/128, M/128). dynamic smem = 65536 B.
// ---------------------------------------------------------------------------
template<bool BIAS_ROW, bool OUT_HALF>
__global__ __launch_bounds__(256, 1)
void gemm_h(const __half* __restrict__ A, const __half* __restrict__ B,
            const float* __restrict__ bias, void* __restrict__ Cv, size_t ldc) {
    extern __shared__ __align__(16) char dsm[];   // [stage][A 16KB | B 16KB]
    const int tid = threadIdx.x, lane = tid & 31, wid = tid >> 5;
    const int g = lane >> 2, tg = lane & 3;
    const int wm = wid & 3, wn = wid >> 2;
    const size_t bm = (size_t)blockIdx.y * 128, bn = (size_t)blockIdx.x * 128;

    const __half* Ag = A + bm * HDIM;
    const __half* Bg = B + bn * HDIM;
    const unsigned sbase = (unsigned)__cvta_generic_to_shared(dsm);

    float acc[2][8][4] = {};

    // issue one k-tile (64 halves deep) into stage s
    auto issue = [&](int kt, int s) {
        unsigned da = sbase + s * 32768, db = da + 16384;
#pragma unroll
        for (int i = 0; i < 4; i++) {
            int idx = tid + 256 * i;
            int r = idx >> 3, ch = idx & 7;
            unsigned off = r * 128 + (((ch ^ r) & 7) << 4);
            CPA(da + off, Ag + (size_t)r * HDIM + kt * 64 + ch * 8);
            CPA(db + off, Bg + (size_t)r * HDIM + kt * 64 + ch * 8);
        }
        CPA_COMMIT();
    };

    issue(0, 0);
    for (int kt = 0; kt < 16; kt++) {
        if (kt + 1 < 16) { issue(kt + 1, (kt + 1) & 1); CPA_WAIT1(); }
        else             { CPA_WAIT0(); }
        __syncthreads();

        const char* sa = dsm + (kt & 1) * 32768;
        const char* sb = sa + 16384;
#pragma unroll
        for (int ks = 0; ks < 4; ks++) {
            const int c0 = ks * 32 + tg * 4;
            unsigned af[2][4];
#pragma unroll
            for (int mt = 0; mt < 2; mt++) {
                int r = wm * 32 + mt * 16 + g;
                af[mt][0] = *(const unsigned*)(sa + swz(r,     c0));
                af[mt][1] = *(const unsigned*)(sa + swz(r + 8, c0));
                af[mt][2] = *(const unsigned*)(sa + swz(r,     c0 + 16));
                af[mt][3] = *(const unsigned*)(sa + swz(r + 8, c0 + 16));
            }
#pragma unroll
            for (int nt = 0; nt < 8; nt++) {
                int n = wn * 64 + nt * 8 + g;
                unsigned b0 = *(const unsigned*)(sb + swz(n, c0));
                unsigned b1 = *(const unsigned*)(sb + swz(n, c0 + 16));
                mma16(acc[0][nt], af[0], b0, b1);
                mma16(acc[1][nt], af[1], b0, b1);
            }
        }
        __syncthreads();
    }

    // epilogue
#pragma unroll
    for (int mt = 0; mt < 2; mt++) {
        size_t r0 = bm + wm * 32 + mt * 16 + g;
#pragma unroll
        for (int nt = 0; nt < 8; nt++) {
            size_t n = bn + wn * 64 + nt * 8 + 2 * tg;
            float b00, b01, b10, b11;
            if (BIAS_ROW) { b00 = b01 = bias[r0]; b10 = b11 = bias[r0 + 8]; }
            else          { b00 = b10 = bias[n];  b01 = b11 = bias[n + 1]; }
            float c0 = acc[mt][nt][0] + b00, c1 = acc[mt][nt][1] + b01;
            float c2 = acc[mt][nt][2] + b10, c3 = acc[mt][nt][3] + b11;
            if (OUT_HALF) {
                __half* C = (__half*)Cv;
                *(__half2*)&C[r0 * ldc + n]       = __floats2half2_rn(c0, c1);
                *(__half2*)&C[(r0 + 8) * ldc + n] = __floats2half2_rn(c2, c3);
            } else {
                float* C = (float*)Cv;
                *(float2*)&C[r0 * ldc + n]       = make_float2(c0, c1);
                *(float2*)&C[(r0 + 8) * ldc + n] = make_float2(c2, c3);
            }
        }
    }
}

// ---------------------------------------------------------------------------
// Flash attention, fp16 operands / fp32 softmax+accum.
// CTA: 128 threads (4 warps), q-tile 128 rows (32 rows/warp, mt=2).
// KV tiles of 64 via cp.async double buffer; V consumed pre-transposed (g_vt16)
// so PV B-fragments are contiguous half2. P stays in registers (S C-fragment
// layout == PV A-fragment layout for m16n8k16). grid = (SEQ/128, NHEAD, BATCH).
// ---------------------------------------------------------------------------
__global__ __launch_bounds__(128, 1)
void attn_h(const __half* __restrict__ q, const __half* __restrict__ k,
            const __half* __restrict__ vt, const float* __restrict__ mask,
            __half* __restrict__ ctx) {
    __shared__ __align__(16) __half Ks[2][64 * 64];
    __shared__ __align__(16) __half Vs[2][64 * 64];
    __shared__ __align__(16) float  Msk[2][64];

    const int b = blockIdx.z, h = blockIdx.y, qt = blockIdx.x;
    const int tid = threadIdx.x, lane = tid & 31, wid = tid >> 5;
    const int g = lane >> 2, tg = lane & 3;

    const float LOG2E = 1.4426950408889634f;
    const float C1 = 0.125f * LOG2E;    // 1/sqrt(64) * log2(e)

    const __half* kbase  = k  + (size_t)(b * SEQ) * HDIM + h * HEADD;
    const __half* vtbase = vt + (size_t)(h * HEADD) * BSROWS + (size_t)b * SEQ;
    const float*  mbase  = mask + (size_t)b * SEQ;

    const unsigned skb = (unsigned)__cvta_generic_to_shared(Ks);
    const unsigned svb = (unsigned)__cvta_generic_to_shared(Vs);
    const unsigned smb = (unsigned)__cvta_generic_to_shared(Msk);

    auto issue = [&](int kt, int s) {
        unsigned dk = skb + s * 8192, dv = svb + s * 8192;
#pragma unroll
        for (int i = 0; i < 4; i++) {
            int idx = tid + 128 * i;
            int r = idx >> 3, ch = idx & 7;
            unsigned off = r * 128 + (((ch ^ r) & 7) << 4);
            CPA(dk + off, kbase + (size_t)(kt * 64 + r) * HDIM + ch * 8);
            CPA(dv + off, vtbase + (size_t)r * BSROWS + kt * 64 + ch * 8);
        }
        if (tid < 16) CPA(smb + s * 256 + tid * 16, mbase + kt * 64 + tid * 4);
        CPA_COMMIT();
    };

    // Q fragments: registers for the whole KV loop
    const __half* qp = q + (size_t)(b * SEQ + qt * 128 + wid * 32) * HDIM + h * HEADD;
    unsigned qf[2][4][4];
#pragma unroll
    for (int mt = 0; mt < 2; mt++)
#pragma unroll
        for (int ks = 0; ks < 4; ks++) {
            const __half* p = qp + (size_t)(mt * 16 + g) * HDIM + ks * 16 + 2 * tg;
            qf[mt][ks][0] = *(const unsigned*)(p);
            qf[mt][ks][1] = *(const unsigned*)(p + 8 * HDIM);
            qf[mt][ks][2] = *(const unsigned*)(p + 8);
            qf[mt][ks][3] = *(const unsigned*)(p + 8 * HDIM + 8);
        }

    float oacc[2][8][4] = {};
    float m[2][2] = {{-1e30f, -1e30f}, {-1e30f, -1e30f}};
    float l[2][2] = {};

    issue(0, 0);
    for (int kt = 0; kt < SEQ / 64; kt++) {
        if (kt + 1 < SEQ / 64) { issue(kt + 1, (kt + 1) & 1); CPA_WAIT1(); }
        else                   { CPA_WAIT0(); }
        __syncthreads();
        const int s = kt & 1;
        const char* sk = (const char*)Ks[s];
        const char* sv = (const char*)Vs[s];

        // ---- S = Q @ K^T ----
        float sacc[2][8][4] = {};
#pragma unroll
        for (int ks = 0; ks < 4; ks++) {
            const int c0 = ks * 32 + tg * 4;
#pragma unroll
            for (int nt = 0; nt < 8; nt++) {
                int n = nt * 8 + g;
                unsigned b0 = *(const unsigned*)(sk + swz(n, c0));
                unsigned b1 = *(const unsigned*)(sk + swz(n, c0 + 16));
                mma16(sacc[0][nt], qf[0][ks], b0, b1);
                mma16(sacc[1][nt], qf[1][ks], b0, b1);
            }
        }

        // ---- mask values (shared across mt) ----
        float mk[8][2];
#pragma unroll
        for (int nt = 0; nt < 8; nt++) {
            mk[nt][0] = Msk[s][nt * 8 + 2 * tg] * LOG2E;
            mk[nt][1] = Msk[s][nt * 8 + 2 * tg + 1] * LOG2E;
        }

        // ---- online softmax (exp2 domain) ----
#pragma unroll
        for (int mt = 0; mt < 2; mt++) {
            float rm0 = -1e30f, rm1 = -1e30f;
#pragma unroll
            for (int nt = 0; nt < 8; nt++) {
                sacc[mt][nt][0] = fmaf(sacc[mt][nt][0], C1, mk[nt][0]);
                sacc[mt][nt][1] = fmaf(sacc[mt][nt][1], C1, mk[nt][1]);
                sacc[mt][nt][2] = fmaf(sacc[mt][nt][2], C1, mk[nt][0]);
                sacc[mt][nt][3] = fmaf(sacc[mt][nt][3], C1, mk[nt][1]);
                rm0 = fmaxf(rm0, fmaxf(sacc[mt][nt][0], sacc[mt][nt][1]));
                rm1 = fmaxf(rm1, fmaxf(sacc[mt][nt][2], sacc[mt][nt][3]));
            }
            rm0 = fmaxf(rm0, __shfl_xor_sync(~0u, rm0, 1));
            rm0 = fmaxf(rm0, __shfl_xor_sync(~0u, rm0, 2));
            rm1 = fmaxf(rm1, __shfl_xor_sync(~0u, rm1, 1));
            rm1 = fmaxf(rm1, __shfl_xor_sync(~0u, rm1, 2));

            float mn0 = fmaxf(m[mt][0], rm0), mn1 = fmaxf(m[mt][1], rm1);
            float sc0 = ex2(m[mt][0] - mn0), sc1 = ex2(m[mt][1] - mn1);
            m[mt][0] = mn0; m[mt][1] = mn1;

            float rs0 = 0.f, rs1 = 0.f;
#pragma unroll
            for (int nt = 0; nt < 8; nt++) {
                sacc[mt][nt][0] = ex2(sacc[mt][nt][0] - mn0);
                sacc[mt][nt][1] = ex2(sacc[mt][nt][1] - mn0);
                sacc[mt][nt][2] = ex2(sacc[mt][nt][2] - mn1);
                sacc[mt][nt][3] = ex2(sacc[mt][nt][3] - mn1);
                rs0 += sacc[mt][nt][0] + sacc[mt][nt][1];
                rs1 += sacc[mt][nt][2] + sacc[mt][nt][3];
                oacc[mt][nt][0] *= sc0; oacc[mt][nt][1] *= sc0;
                oacc[mt][nt][2] *= sc1; oacc[mt][nt][3] *= sc1;
            }
            rs0 += __shfl_xor_sync(~0u, rs0, 1);
            rs0 += __shfl_xor_sync(~0u, rs0, 2);
            rs1 += __shfl_xor_sync(~0u, rs1, 1);
            rs1 += __shfl_xor_sync(~0u, rs1, 2);
            l[mt][0] = l[mt][0] * sc0 + rs0;
            l[mt][1] = l[mt][1] * sc1 + rs1;
        }

        // ---- O += P @ V : P packed straight from sacc registers ----
#pragma unroll
        for (int ks = 0; ks < 4; ks++) {
            unsigned pf[2][4];
#pragma unroll
            for (int mt = 0; mt < 2; mt++) {
                pf[mt][0] = h2pack(sacc[mt][2 * ks][0],     sacc[mt][2 * ks][1]);
                pf[mt][1] = h2pack(sacc[mt][2 * ks][2],     sacc[mt][2 * ks][3]);
                pf[mt][2] = h2pack(sacc[mt][2 * ks + 1][0], sacc[mt][2 * ks + 1][1]);
                pf[mt][3] = h2pack(sacc[mt][2 * ks + 1][2], sacc[mt][2 * ks + 1][3]);
            }
            const int c0 = ks * 32 + tg * 4;
#pragma unroll
            for (int nt = 0; nt < 8; nt++) {
                int n = nt * 8 + g;
                unsigned b0 = *(const unsigned*)(sv + swz(n, c0));
                unsigned b1 = *(const unsigned*)(sv + swz(n, c0 + 16));
                mma16(oacc[0][nt], pf[0], b0, b1);
                mma16(oacc[1][nt], pf[1], b0, b1);
            }
        }
        __syncthreads();
    }

    // ---- epilogue: O / l -> ctx16 ----
#pragma unroll
    for (int mt = 0; mt < 2; mt++) {
        float inv0 = 1.f / l[mt][0], inv1 = 1.f / l[mt][1];
        size_t r0 = (size_t)(b * SEQ + qt * 128 + wid * 32 + mt * 16 + g);
#pragma unroll
        for (int nt = 0; nt < 8; nt++) {
            size_t c = (size_t)(h * HEADD + nt * 8 + 2 * tg);
            *(__half2*)&ctx[r0 * HDIM + c] =
                __floats2half2_rn(oacc[mt][nt][0] * inv0, oacc[mt][nt][1] * inv0);
            *(__half2*)&ctx[(r0 + 8) * HDIM + c] =
                __floats2half2_rn(oacc[mt][nt][2] * inv1, oacc[mt][nt][3] * inv1);
        }
    }
}

// ---------------------------------------------------------------------------
// launch
// ---------------------------------------------------------------------------
extern "C" void kernel_launch(void* const* d_in, const int* in_sizes, int n_in,
                              void* d_out, int out_size) {
    const float* hs   = (const float*)d_in[0];
    const float* mask = (const float*)d_in[1];
    const float* Wq   = (const float*)d_in[2];
    const float* bq   = (const float*)d_in[3];
    const float* Wk   = (const float*)d_in[4];
    const float* bk   = (const float*)d_in[5];
    const float* Wv   = (const float*)d_in[6];
    const float* bv   = (const float*)d_in[7];
    const float* Wo   = (const float*)d_in[8];
    const float* bo   = (const float*)d_in[9];
    float* out = (float*)d_out;

    __half *hs16, *wq16, *wk16, *wv16, *wo16, *q16, *k16, *vt16, *ctx16;
    cudaGetSymbolAddress((void**)&hs16,  g_hs16);
    cudaGetSymbolAddress((void**)&wq16,  g_wq16);
    cudaGetSymbolAddress((void**)&wk16,  g_wk16);
    cudaGetSymbolAddress((void**)&wv16,  g_wv16);
    cudaGetSymbolAddress((void**)&wo16,  g_wo16);
    cudaGetSymbolAddress((void**)&q16,   g_q16);
    cudaGetSymbolAddress((void**)&k16,   g_k16);
    cudaGetSymbolAddress((void**)&vt16,  g_vt16);
    cudaGetSymbolAddress((void**)&ctx16, g_ctx16);

    const int GSM = 65536;
    cudaFuncSetAttribute(gemm_h<false, true>,  cudaFuncAttributeMaxDynamicSharedMemorySize, GSM);
    cudaFuncSetAttribute(gemm_h<true,  true>,  cudaFuncAttributeMaxDynamicSharedMemorySize, GSM);
    cudaFuncSetAttribute(gemm_h<false, false>, cudaFuncAttributeMaxDynamicSharedMemorySize, GSM);

    // fp32 -> fp16 converts
    cvt_kernel<<<512, 256>>>(hs, hs16, BSROWS * HDIM / 4);
    cvt_kernel<<<128, 256>>>(Wq, wq16, HDIM * HDIM / 4);
    cvt_kernel<<<128, 256>>>(Wk, wk16, HDIM * HDIM / 4);
    cvt_kernel<<<128, 256>>>(Wv, wv16, HDIM * HDIM / 4);
    cvt_kernel<<<128, 256>>>(Wo, wo16, HDIM * HDIM / 4);

    // Q, K: [8192,1024] = hs @ W^T + b
    dim3 gqk(HDIM / 128, BSROWS / 128);            // (8, 64)
    gemm_h<false, true><<<gqk, 256, GSM>>>(hs16, wq16, bq, q16, HDIM);
    gemm_h<false, true><<<gqk, 256, GSM>>>(hs16, wk16, bk, k16, HDIM);

    // V^T: [1024, 8192] = Wv @ hs^T + bv (bias per row)
    dim3 gvt(BSROWS / 128, HDIM / 128);            // (64, 8)
    gemm_h<true, true><<<gvt, 256, GSM>>>(wv16, hs16, bv, vt16, BSROWS);

    // attention
    dim3 ga(SEQ / 128, NHEAD, BATCH);              // (16, 16, 4)
    attn_h<<<ga, 128>>>(q16, k16, vt16, mask, ctx16);

    // out = ctx @ Wo^T + bo (fp32 output)
    gemm_h<false, false><<<gqk, 256, GSM>>>(ctx16, wo16, bo, out, HDIM);
}

// round 5
// speedup vs baseline: 2.6458x; 1.0149x over previous
#include <cuda_runtime.h>
#include <cuda_fp16.h>

#define HDIM   1024
#define NHEAD  16
#define HEADD  64
#define BATCH  4
#define SEQ    2048
#define BSROWS (BATCH * SEQ)   // 8192

// fp16 scratch (allocation-free rule: __device__ globals)
__device__ __half g_hs16[(size_t)BSROWS * HDIM];
__device__ __half g_wq16[(size_t)HDIM * HDIM];
__device__ __half g_wk16[(size_t)HDIM * HDIM];
__device__ __half g_wv16[(size_t)HDIM * HDIM];
__device__ __half g_wo16[(size_t)HDIM * HDIM];
__device__ __half g_q16[(size_t)BSROWS * HDIM];
__device__ __half g_k16[(size_t)BSROWS * HDIM];
__device__ __half g_vt16[(size_t)HDIM * BSROWS];   // [dim][b*S+s]
__device__ __half g_ctx16[(size_t)BSROWS * HDIM];

// ---------------------------------------------------------------------------
// helpers
// ---------------------------------------------------------------------------
__device__ __forceinline__ void mma16(float* c, const unsigned* a, unsigned b0, unsigned b1) {
    asm volatile(
        "mma.sync.aligned.m16n8k16.row.col.f32.f16.f16.f32 "
        "{%0,%1,%2,%3}, {%4,%5,%6,%7}, {%8,%9}, {%0,%1,%2,%3};"
        : "+f"(c[0]), "+f"(c[1]), "+f"(c[2]), "+f"(c[3])
        : "r"(a[0]), "r"(a[1]), "r"(a[2]), "r"(a[3]), "r"(b0), "r"(b1));
}

// ldmatrix x4: 4 8x8 b16 matrices. Matrix i taken from lanes [8i, 8i+8)'s
// addresses. With addr(lane) = base_row + (lane & 15), chunk + (lane & 16):
//   r0 = rows[0:8)  k[0:8)   r1 = rows[8:16) k[0:8)
//   r2 = rows[0:8)  k[8:16)  r3 = rows[8:16) k[8:16)
__device__ __forceinline__ void ldsm4(unsigned* r, unsigned addr) {
    asm volatile("ldmatrix.sync.aligned.m8n8.x4.shared.b16 {%0,%1,%2,%3}, [%4];"
                 : "=r"(r[0]), "=r"(r[1]), "=r"(r[2]), "=r"(r[3]) : "r"(addr));
}

__device__ __forceinline__ float ex2(float x) {
    float r;
    asm("ex2.approx.ftz.f32 %0, %1;" : "=f"(r) : "f"(x));
    return r;
}

// XOR swizzle: 128B logical rows, 16B chunks, chunk ^= (row & 7). Conflict-free
// for cp.async 16B stores and for ldmatrix (8 lanes of a matrix span 8 rows ->
// 8 distinct chunk columns).
__device__ __forceinline__ int swz(int r, int cbyte) {
    return r * 128 + ((((cbyte >> 4) ^ r) & 7) << 4) + (cbyte & 15);
}

#define CPA(dst, src) \
    asm volatile("cp.async.cg.shared.global [%0], [%1], 16;" :: "r"(dst), "l"(src))
#define CPA_COMMIT() asm volatile("cp.async.commit_group;" ::)
#define CPA_WAIT1()  asm volatile("cp.async.wait_group 1;" ::)
#define CPA_WAIT0()  asm volatile("cp.async.wait_group 0;" ::)

__device__ __forceinline__ unsigned h2pack(float lo, float hi) {
    __half2 h = __floats2half2_rn(lo, hi);
    return *(unsigned*)&h;
}

// ---------------------------------------------------------------------------
// fp32 -> fp16 convert
// ---------------------------------------------------------------------------
__global__ void cvt_kernel(const float* __restrict__ s, __half* __restrict__ d, int n4) {
    int stride = gridDim.x * blockDim.x;
    for (int i = blockIdx.x * blockDim.x + threadIdx.x; i < n4; i += stride) {
        float4 v = ((const float4*)s)[i];
        __half2 h0 = __floats2half2_rn(v.x, v.y);
        __half2 h1 = __floats2half2_rn(v.z, v.w);
        ((uint2*)d)[i] = make_uint2(*(unsigned*)&h0, *(unsigned*)&h1);
    }
}

// ---------------------------------------------------------------------------
// fp16 GEMM: C[m,n] = sum_k A[m,k]*B[n,k] + bias, K=1024, lda=ldb=1024.
// Tile 128x128xk64, 256 threads (8 warps: 4M x 2N, warp tile 32x64, mt=2).
// cp.async double buffer, swizzled smem, ldmatrix fragments, m16n8k16.
// grid = (N/128, M/128). dynamic smem = 65536 B.
// ---------------------------------------------------------------------------
template<bool BIAS_ROW, bool OUT_HALF>
__global__ __launch_bounds__(256, 1)
void gemm_h(const __half* __restrict__ A, const __half* __restrict__ B,
            const float* __restrict__ bias, void* __restrict__ Cv, size_t ldc) {
    extern __shared__ __align__(16) char dsm[];   // [stage][A 16KB | B 16KB]
    const int tid = threadIdx.x, lane = tid & 31, wid = tid >> 5;
    const int g = lane >> 2, tg = lane & 3;
    const int wm = wid & 3, wn = wid >> 2;
    const int lrow = lane & 15, lch = lane & 16;
    const size_t bm = (size_t)blockIdx.y * 128, bn = (size_t)blockIdx.x * 128;

    const __half* Ag = A + bm * HDIM;
    const __half* Bg = B + bn * HDIM;
    const unsigned sbase = (unsigned)__cvta_generic_to_shared(dsm);

    float acc[2][8][4] = {};

    // issue one k-tile (64 halves deep) into stage s
    auto issue = [&](int kt, int s) {
        unsigned da = sbase + s * 32768, db = da + 16384;
#pragma unroll
        for (int i = 0; i < 4; i++) {
            int idx = tid + 256 * i;
            int r = idx >> 3, ch = idx & 7;
            unsigned off = r * 128 + (((ch ^ r) & 7) << 4);
            CPA(da + off, Ag + (size_t)r * HDIM + kt * 64 + ch * 8);
            CPA(db + off, Bg + (size_t)r * HDIM + kt * 64 + ch * 8);
        }
        CPA_COMMIT();
    };

    issue(0, 0);
    for (int kt = 0; kt < 16; kt++) {
        if (kt + 1 < 16) { issue(kt + 1, (kt + 1) & 1); CPA_WAIT1(); }
        else             { CPA_WAIT0(); }
        __syncthreads();

        const unsigned sa = sbase + (kt & 1) * 32768;
        const unsigned sb = sa + 16384;
#pragma unroll
        for (int ks = 0; ks < 4; ks++) {
            const int cb = ks * 32 + lch;
            unsigned af[2][4], bf[4][4];
#pragma unroll
            for (int mt = 0; mt < 2; mt++)
                ldsm4(af[mt], sa + swz(wm * 32 + mt * 16 + lrow, cb));
#pragma unroll
            for (int np = 0; np < 4; np++)
                ldsm4(bf[np], sb + swz(wn * 64 + np * 16 + lrow, cb));
#pragma unroll
            for (int np = 0; np < 4; np++) {
                mma16(acc[0][2 * np],     af[0], bf[np][0], bf[np][2]);
                mma16(acc[1][2 * np],     af[1], bf[np][0], bf[np][2]);
                mma16(acc[0][2 * np + 1], af[0], bf[np][1], bf[np][3]);
                mma16(acc[1][2 * np + 1], af[1], bf[np][1], bf[np][3]);
            }
        }
        __syncthreads();
    }

    // epilogue
#pragma unroll
    for (int mt = 0; mt < 2; mt++) {
        size_t r0 = bm + wm * 32 + mt * 16 + g;
#pragma unroll
        for (int nt = 0; nt < 8; nt++) {
            size_t n = bn + wn * 64 + nt * 8 + 2 * tg;
            float b00, b01, b10, b11;
            if (BIAS_ROW) { b00 = b01 = bias[r0]; b10 = b11 = bias[r0 + 8]; }
            else          { b00 = b10 = bias[n];  b01 = b11 = bias[n + 1]; }
            float c0 = acc[mt][nt][0] + b00, c1 = acc[mt][nt][1] + b01;
            float c2 = acc[mt][nt][2] + b10, c3 = acc[mt][nt][3] + b11;
            if (OUT_HALF) {
                __half* C = (__half*)Cv;
                *(__half2*)&C[r0 * ldc + n]       = __floats2half2_rn(c0, c1);
                *(__half2*)&C[(r0 + 8) * ldc + n] = __floats2half2_rn(c2, c3);
            } else {
                float* C = (float*)Cv;
                *(float2*)&C[r0 * ldc + n]       = make_float2(c0, c1);
                *(float2*)&C[(r0 + 8) * ldc + n] = make_float2(c2, c3);
            }
        }
    }
}

// ---------------------------------------------------------------------------
// Flash attention, fp16 operands / fp32 softmax+accum.
// CTA: 128 threads (4 warps), q-tile 128 rows (32 rows/warp, mt=2).
// KV tiles of 64 via cp.async double buffer; ldmatrix K/V fragments; V
// pre-transposed (g_vt16); P stays in registers. grid = (SEQ/128, NHEAD, BATCH).
// ---------------------------------------------------------------------------
__global__ __launch_bounds__(128, 1)
void attn_h(const __half* __restrict__ q, const __half* __restrict__ k,
            const __half* __restrict__ vt, const float* __restrict__ mask,
            __half* __restrict__ ctx) {
    __shared__ __align__(16) __half Ks[2][64 * 64];
    __shared__ __align__(16) __half Vs[2][64 * 64];
    __shared__ __align__(16) float  Msk[2][64];

    const int b = blockIdx.z, h = blockIdx.y, qt = blockIdx.x;
    const int tid = threadIdx.x, lane = tid & 31, wid = tid >> 5;
    const int g = lane >> 2, tg = lane & 3;
    const int lrow = lane & 15, lch = lane & 16;

    const float LOG2E = 1.4426950408889634f;
    const float C1 = 0.125f * LOG2E;    // 1/sqrt(64) * log2(e)

    const __half* kbase  = k  + (size_t)(b * SEQ) * HDIM + h * HEADD;
    const __half* vtbase = vt + (size_t)(h * HEADD) * BSROWS + (size_t)b * SEQ;
    const float*  mbase  = mask + (size_t)b * SEQ;

    const unsigned skb = (unsigned)__cvta_generic_to_shared(Ks);
    const unsigned svb = (unsigned)__cvta_generic_to_shared(Vs);
    const unsigned smb = (unsigned)__cvta_generic_to_shared(Msk);

    auto issue = [&](int kt, int s) {
        unsigned dk = skb + s * 8192, dv = svb + s * 8192;
#pragma unroll
        for (int i = 0; i < 4; i++) {
            int idx = tid + 128 * i;
            int r = idx >> 3, ch = idx & 7;
            unsigned off = r * 128 + (((ch ^ r) & 7) << 4);
            CPA(dk + off, kbase + (size_t)(kt * 64 + r) * HDIM + ch * 8);
            CPA(dv + off, vtbase + (size_t)r * BSROWS + kt * 64 + ch * 8);
        }
        if (tid < 16) CPA(smb + s * 256 + tid * 16, mbase + kt * 64 + tid * 4);
        CPA_COMMIT();
    };

    // Q fragments: registers for the whole KV loop
    const __half* qp = q + (size_t)(b * SEQ + qt * 128 + wid * 32) * HDIM + h * HEADD;
    unsigned qf[2][4][4];
#pragma unroll
    for (int mt = 0; mt < 2; mt++)
#pragma unroll
        for (int ks = 0; ks < 4; ks++) {
            const __half* p = qp + (size_t)(mt * 16 + g) * HDIM + ks * 16 + 2 * tg;
            qf[mt][ks][0] = *(const unsigned*)(p);
            qf[mt][ks][1] = *(const unsigned*)(p + 8 * HDIM);
            qf[mt][ks][2] = *(const unsigned*)(p + 8);
            qf[mt][ks][3] = *(const unsigned*)(p + 8 * HDIM + 8);
        }

    float oacc[2][8][4] = {};
    float m[2][2] = {{-1e30f, -1e30f}, {-1e30f, -1e30f}};
    float l[2][2] = {};

    issue(0, 0);
    for (int kt = 0; kt < SEQ / 64; kt++) {
        if (kt + 1 < SEQ / 64) { issue(kt + 1, (kt + 1) & 1); CPA_WAIT1(); }
        else                   { CPA_WAIT0(); }
        __syncthreads();
        const int s = kt & 1;
        const unsigned sk = skb + s * 8192;
        const unsigned sv = svb + s * 8192;

        // ---- S = Q @ K^T ----
        float sacc[2][8][4] = {};
#pragma unroll
        for (int ks = 0; ks < 4; ks++) {
            const int cb = ks * 32 + lch;
#pragma unroll
            for (int np = 0; np < 4; np++) {
                unsigned bf[4];
                ldsm4(bf, sk + swz(np * 16 + lrow, cb));
                mma16(sacc[0][2 * np],     qf[0][ks], bf[0], bf[2]);
                mma16(sacc[1][2 * np],     qf[1][ks], bf[0], bf[2]);
                mma16(sacc[0][2 * np + 1], qf[0][ks], bf[1], bf[3]);
                mma16(sacc[1][2 * np + 1], qf[1][ks], bf[1], bf[3]);
            }
        }

        // ---- mask values (shared across mt) ----
        float mk[8][2];
#pragma unroll
        for (int nt = 0; nt < 8; nt++) {
            mk[nt][0] = Msk[s][nt * 8 + 2 * tg] * LOG2E;
            mk[nt][1] = Msk[s][nt * 8 + 2 * tg + 1] * LOG2E;
        }

        // ---- online softmax (exp2 domain) ----
#pragma unroll
        for (int mt = 0; mt < 2; mt++) {
            float rm0 = -1e30f, rm1 = -1e30f;
#pragma unroll
            for (int nt = 0; nt < 8; nt++) {
                sacc[mt][nt][0] = fmaf(sacc[mt][nt][0], C1, mk[nt][0]);
                sacc[mt][nt][1] = fmaf(sacc[mt][nt][1], C1, mk[nt][1]);
                sacc[mt][nt][2] = fmaf(sacc[mt][nt][2], C1, mk[nt][0]);
                sacc[mt][nt][3] = fmaf(sacc[mt][nt][3], C1, mk[nt][1]);
                rm0 = fmaxf(rm0, fmaxf(sacc[mt][nt][0], sacc[mt][nt][1]));
                rm1 = fmaxf(rm1, fmaxf(sacc[mt][nt][2], sacc[mt][nt][3]));
            }
            rm0 = fmaxf(rm0, __shfl_xor_sync(~0u, rm0, 1));
            rm0 = fmaxf(rm0, __shfl_xor_sync(~0u, rm0, 2));
            rm1 = fmaxf(rm1, __shfl_xor_sync(~0u, rm1, 1));
            rm1 = fmaxf(rm1, __shfl_xor_sync(~0u, rm1, 2));

            float mn0 = fmaxf(m[mt][0], rm0), mn1 = fmaxf(m[mt][1], rm1);
            float sc0 = ex2(m[mt][0] - mn0), sc1 = ex2(m[mt][1] - mn1);
            m[mt][0] = mn0; m[mt][1] = mn1;

            float rs0 = 0.f, rs1 = 0.f;
#pragma unroll
            for (int nt = 0; nt < 8; nt++) {
                sacc[mt][nt][0] = ex2(sacc[mt][nt][0] - mn0);
                sacc[mt][nt][1] = ex2(sacc[mt][nt][1] - mn0);
                sacc[mt][nt][2] = ex2(sacc[mt][nt][2] - mn1);
                sacc[mt][nt][3] = ex2(sacc[mt][nt][3] - mn1);
                rs0 += sacc[mt][nt][0] + sacc[mt][nt][1];
                rs1 += sacc[mt][nt][2] + sacc[mt][nt][3];
                oacc[mt][nt][0] *= sc0; oacc[mt][nt][1] *= sc0;
                oacc[mt][nt][2] *= sc1; oacc[mt][nt][3] *= sc1;
            }
            rs0 += __shfl_xor_sync(~0u, rs0, 1);
            rs0 += __shfl_xor_sync(~0u, rs0, 2);
            rs1 += __shfl_xor_sync(~0u, rs1, 1);
            rs1 += __shfl_xor_sync(~0u, rs1, 2);
            l[mt][0] = l[mt][0] * sc0 + rs0;
            l[mt][1] = l[mt][1] * sc1 + rs1;
        }

        // ---- O += P @ V : P packed straight from sacc registers ----
#pragma unroll
        for (int ks = 0; ks < 4; ks++) {
            unsigned pf[2][4];
#pragma unroll
            for (int mt = 0; mt < 2; mt++) {
                pf[mt][0] = h2pack(sacc[mt][2 * ks][0],     sacc[mt][2 * ks][1]);
                pf[mt][1] = h2pack(sacc[mt][2 * ks][2],     sacc[mt][2 * ks][3]);
                pf[mt][2] = h2pack(sacc[mt][2 * ks + 1][0], sacc[mt][2 * ks + 1][1]);
                pf[mt][3] = h2pack(sacc[mt][2 * ks + 1][2], sacc[mt][2 * ks + 1][3]);
            }
            const int cb = ks * 32 + lch;
#pragma unroll
            for (int np = 0; np < 4; np++) {
                unsigned bf[4];
                ldsm4(bf, sv + swz(np * 16 + lrow, cb));
                mma16(oacc[0][2 * np],     pf[0], bf[0], bf[2]);
                mma16(oacc[1][2 * np],     pf[1], bf[0], bf[2]);
                mma16(oacc[0][2 * np + 1], pf[0], bf[1], bf[3]);
                mma16(oacc[1][2 * np + 1], pf[1], bf[1], bf[3]);
            }
        }
        __syncthreads();
    }

    // ---- epilogue: O / l -> ctx16 ----
#pragma unroll
    for (int mt = 0; mt < 2; mt++) {
        float inv0 = 1.f / l[mt][0], inv1 = 1.f / l[mt][1];
        size_t r0 = (size_t)(b * SEQ + qt * 128 + wid * 32 + mt * 16 + g);
#pragma unroll
        for (int nt = 0; nt < 8; nt++) {
            size_t c = (size_t)(h * HEADD + nt * 8 + 2 * tg);
            *(__half2*)&ctx[r0 * HDIM + c] =
                __floats2half2_rn(oacc[mt][nt][0] * inv0, oacc[mt][nt][1] * inv0);
            *(__half2*)&ctx[(r0 + 8) * HDIM + c] =
                __floats2half2_rn(oacc[mt][nt][2] * inv1, oacc[mt][nt][3] * inv1);
        }
    }
}

// ---------------------------------------------------------------------------
// launch
// ---------------------------------------------------------------------------
extern "C" void kernel_launch(void* const* d_in, const int* in_sizes, int n_in,
                              void* d_out, int out_size) {
    const float* hs   = (const float*)d_in[0];
    const float* mask = (const float*)d_in[1];
    const float* Wq   = (const float*)d_in[2];
    const float* bq   = (const float*)d_in[3];
    const float* Wk   = (const float*)d_in[4];
    const float* bk   = (const float*)d_in[5];
    const float* Wv   = (const float*)d_in[6];
    const float* bv   = (const float*)d_in[7];
    const float* Wo   = (const float*)d_in[8];
    const float* bo   = (const float*)d_in[9];
    float* out = (float*)d_out;

    __half *hs16, *wq16, *wk16, *wv16, *wo16, *q16, *k16, *vt16, *ctx16;
    cudaGetSymbolAddress((void**)&hs16,  g_hs16);
    cudaGetSymbolAddress((void**)&wq16,  g_wq16);
    cudaGetSymbolAddress((void**)&wk16,  g_wk16);
    cudaGetSymbolAddress((void**)&wv16,  g_wv16);
    cudaGetSymbolAddress((void**)&wo16,  g_wo16);
    cudaGetSymbolAddress((void**)&q16,   g_q16);
    cudaGetSymbolAddress((void**)&k16,   g_k16);
    cudaGetSymbolAddress((void**)&vt16,  g_vt16);
    cudaGetSymbolAddress((void**)&ctx16, g_ctx16);

    const int GSM = 65536;
    cudaFuncSetAttribute(gemm_h<false, true>,  cudaFuncAttributeMaxDynamicSharedMemorySize, GSM);
    cudaFuncSetAttribute(gemm_h<true,  true>,  cudaFuncAttributeMaxDynamicSharedMemorySize, GSM);
    cudaFuncSetAttribute(gemm_h<false, false>, cudaFuncAttributeMaxDynamicSharedMemorySize, GSM);

    // fp32 -> fp16 converts
    cvt_kernel<<<512, 256>>>(hs, hs16, BSROWS * HDIM / 4);
    cvt_kernel<<<128, 256>>>(Wq, wq16, HDIM * HDIM / 4);
    cvt_kernel<<<128, 256>>>(Wk, wk16, HDIM * HDIM / 4);
    cvt_kernel<<<128, 256>>>(Wv, wv16, HDIM * HDIM / 4);
    cvt_kernel<<<128, 256>>>(Wo, wo16, HDIM * HDIM / 4);

    // Q, K: [8192,1024] = hs @ W^T + b
    dim3 gqk(HDIM / 128, BSROWS / 128);            // (8, 64)
    gemm_h<false, true><<<gqk, 256, GSM>>>(hs16, wq16, bq, q16, HDIM);
    gemm_h<false, true><<<gqk, 256, GSM>>>(hs16, wk16, bk, k16, HDIM);

    // V^T: [1024, 8192] = Wv @ hs^T + bv (bias per row)
    dim3 gvt(BSROWS / 128, HDIM / 128);            // (64, 8)
    gemm_h<true, true><<<gvt, 256, GSM>>>(wv16, hs16, bv, vt16, BSROWS);

    // attention
    dim3 ga(SEQ / 128, NHEAD, BATCH);              // (16, 16, 4)
    attn_h<<<ga, 128>>>(q16, k16, vt16, mask, ctx16);

    // out = ctx @ Wo^T + bo (fp32 output)
    gemm_h<false, false><<<gqk, 256, GSM>>>(ctx16, wo16, bo, out, HDIM);
}